// round 11
// baseline (speedup 1.0000x reference)
#include <cuda_runtime.h>
#include <cstdint>
#include <cstddef>

// Problem constants: B=4, C=128, N=64, HID=1536, PROJ=768
// featT: [128, 768] (k-major for GEMM1), hT: [1536, 768] (k-major for GEMM2)

__device__ float g_featT[128 * 768];
__device__ float g_hT[1536 * 768];

__device__ __forceinline__ void redadd(float* p, float v) {
    asm volatile("red.global.add.f32 [%0], %1;" :: "l"(p), "f"(v) : "memory");
}

// ---------------------------------------------------------------------------
// init: zero featT (24576 f4) and fill out with bias rows (147456 f4).
// ---------------------------------------------------------------------------
__global__ void __launch_bounds__(256) init_kernel(const float* __restrict__ bias,
                                                   float* __restrict__ out) {
    const int i = blockIdx.x * 256 + threadIdx.x;
    if (i < 24576) {
        reinterpret_cast<float4*>(g_featT)[i] = make_float4(0.f, 0.f, 0.f, 0.f);
    } else {
        const int k = i - 24576;
        reinterpret_cast<float4*>(out)[k] =
            reinterpret_cast<const float4*>(bias)[k % 192];
    }
}

// ---------------------------------------------------------------------------
// Kernel 1: streaming reduction, 4096 CTAs (1/8 slab = 8 d-planes, 128 KB).
// Output featT[c][m] (m = b*192 + row), h/w rows via red.global.add.
// ---------------------------------------------------------------------------
__global__ void __launch_bounds__(256, 4) reduce_kernel(const float* __restrict__ x) {
    __shared__ float dpart[8 * 64];
    __shared__ float ss_s[64];
    __shared__ float sa_s[64];
    const int tid = threadIdx.x;
    if (tid < 64) { ss_s[tid] = 0.f; sa_s[tid] = 0.f; }
    __syncthreads();

    const int slab = blockIdx.x >> 3;
    const int p    = blockIdx.x & 7;
    const int warp = tid >> 5;
    const int lane = tid & 31;
    const int q    = warp & 3;
    const int half = warp >> 2;
    const int j    = lane & 15;
    const int u    = lane >> 4;

    const float4* base = reinterpret_cast<const float4*>(x) + (size_t)slab * 65536
                         + (size_t)(8 * p) * 1024 + (16 * q + u) * 16 + j;

    float hreg[8];
#pragma unroll
    for (int i = 0; i < 8; ++i) hreg[i] = 0.f;
    float w0 = 0.f, w1 = 0.f, w2 = 0.f, w3 = 0.f;

#pragma unroll
    for (int dd = 0; dd < 4; ++dd) {
        const int dl = 2 * dd + half;
        const float4* pp = base + dl * 1024;
        float dacc = 0.f;
#pragma unroll
        for (int i = 0; i < 8; ++i) {
            float4 v = __ldcs(pp + i * 32);
            float s0 = v.x * v.x, s1 = v.y * v.y, s2 = v.z * v.z, s3 = v.w * v.w;
            w0 += s0; w1 += s1; w2 += s2; w3 += s3;
            float sm = (s0 + s1) + (s2 + s3);
            hreg[i] += sm;
            dacc    += sm;
        }
        dacc += __shfl_xor_sync(0xffffffffu, dacc, 16);
        if (lane < 16) dpart[dl * 64 + q * 16 + j] = dacc;
    }

#pragma unroll
    for (int i = 0; i < 8; ++i) {
        float v = hreg[i];
        v += __shfl_xor_sync(0xffffffffu, v, 1);
        v += __shfl_xor_sync(0xffffffffu, v, 2);
        v += __shfl_xor_sync(0xffffffffu, v, 4);
        v += __shfl_xor_sync(0xffffffffu, v, 8);
        if (j == 0) atomicAdd(&ss_s[16 * q + u + 2 * i], v);
    }

    atomicAdd(&sa_s[4 * j + 0], w0);
    atomicAdd(&sa_s[4 * j + 1], w1);
    atomicAdd(&sa_s[4 * j + 2], w2);
    atomicAdd(&sa_s[4 * j + 3], w3);

    __syncthreads();

    const int b = slab >> 7;
    const int c = slab & 127;
    float* frow = g_featT + (size_t)c * 768 + b * 192;
    if (tid < 32) {
        const int dl = tid >> 2;
        const int qq = tid & 3;
        const float4* dp = reinterpret_cast<const float4*>(&dpart[dl * 64 + qq * 16]);
        float s = 0.f;
#pragma unroll
        for (int k = 0; k < 4; ++k) {
            float4 v = dp[k];
            s += (v.x + v.y) + (v.z + v.w);
        }
        s += __shfl_xor_sync(0xffffffffu, s, 1);
        s += __shfl_xor_sync(0xffffffffu, s, 2);
        if (qq == 0) frow[8 * p + dl] = s * (1.0f / 4096.0f);
    }
    if (tid < 64) {
        redadd(&frow[64 + tid], ss_s[tid] * (1.0f / 4096.0f));
    } else if (tid < 128) {
        redadd(&frow[128 + (tid - 64)], sa_s[tid - 64] * (1.0f / 4096.0f));
    }
}

// ---------------------------------------------------------------------------
// FFMA2 SGEMM, k-major operands, cp.async staging, 3-STAGE pipeline
// (wait_group 1 keeps one fill in flight across the barrier).
// tile (64*GM)m x (64*GN)n, BK=16, 256 threads.
// Inner loop/warp/k-step: GM A-LDS.128 + GN B-LDS.128 + 4*GN packs +
// 8*GM*GN FFMA2, m-pair f32x2 accumulation.
// TOUT: transposed epilogue bias+relu -> C[n][m] (row stride Mtot).
// !TOUT: scalar red.global.add.f32 into C (pre-filled with bias), split-K z.
// ---------------------------------------------------------------------------
__device__ __forceinline__ void fma2(unsigned long long& d,
                                     unsigned long long a,
                                     unsigned long long b) {
    asm("fma.rn.f32x2 %0, %1, %2, %0;" : "+l"(d) : "l"(a), "l"(b));
}
__device__ __forceinline__ unsigned long long pack2(float v) {
    unsigned long long r;
    asm("mov.b64 %0, {%1, %1};" : "=l"(r) : "f"(v));
    return r;
}
__device__ __forceinline__ float2 u2f(unsigned long long v) {
    float2 f;
    asm("mov.b64 {%0,%1}, %2;" : "=f"(f.x), "=f"(f.y) : "l"(v));
    return f;
}
__device__ __forceinline__ void cp_async16(uint32_t dst, const void* src) {
    asm volatile("cp.async.ca.shared.global [%0], [%1], 16;"
                 :: "r"(dst), "l"(src) : "memory");
}

template <int GM, int GN, bool TOUT>
__global__ void __launch_bounds__(256, 2) gemm_kernel(const float* __restrict__ At,
                                                      const float* __restrict__ Bw,
                                                      const float* __restrict__ bias,
                                                      float* __restrict__ C,
                                                      int Mtot, int Nn, int Kc) {
    constexpr int AROW = 64 * GM;
    constexpr int BROW = 64 * GN;
    __shared__ float As[3][16][AROW];
    __shared__ float Bs[3][16][BROW];

    const int tid = threadIdx.x;
    const int tx = tid & 15;
    const int ty = tid >> 4;
    const int m0 = blockIdx.y * AROW;
    const int n0 = blockIdx.x * BROW;
    const int kstart = blockIdx.z * Kc;
    const int T = Kc >> 4;            // assumed >= 2

    unsigned long long acc[2 * GM][4 * GN];
#pragma unroll
    for (int i = 0; i < 2 * GM; ++i)
#pragma unroll
        for (int qn = 0; qn < 4 * GN; ++qn) acc[i][qn] = 0ull;

    const unsigned as_base = (unsigned)__cvta_generic_to_shared(&As[0][0][0]);
    const unsigned bs_base = (unsigned)__cvta_generic_to_shared(&Bs[0][0][0]);
    const unsigned a_rd = as_base + (unsigned)(ty * 16);
    const unsigned b_rd = bs_base + (unsigned)(tx * 16);
    constexpr unsigned ASTAGE_B = 16 * AROW * 4;
    constexpr unsigned BSTAGE_B = 16 * BROW * 4;

    const float* Abase = At + (size_t)kstart * Mtot + m0;
    const float* Bbase = Bw + (size_t)kstart * Nn + n0;

#define FILL_TILE(stage, trow)                                                 \
    do {                                                                       \
        _Pragma("unroll")                                                      \
        for (int i = 0; i < GM; ++i) {                                         \
            const int idx = tid + 256 * i;                                     \
            const int r = idx / (16 * GM);                                     \
            const int f4 = idx % (16 * GM);                                    \
            cp_async16(as_base + (unsigned)((stage) * ASTAGE_B +               \
                                            (r * AROW + 4 * f4) * 4),          \
                       Abase + (size_t)((trow) + r) * Mtot + 4 * f4);          \
        }                                                                      \
        _Pragma("unroll")                                                      \
        for (int i = 0; i < GN; ++i) {                                         \
            const int idx = tid + 256 * i;                                     \
            const int r = idx / (16 * GN);                                     \
            const int f4 = idx % (16 * GN);                                    \
            cp_async16(bs_base + (unsigned)((stage) * BSTAGE_B +               \
                                            (r * BROW + 4 * f4) * 4),          \
                       Bbase + (size_t)((trow) + r) * Nn + 4 * f4);            \
        }                                                                      \
        asm volatile("cp.async.commit_group;" ::: "memory");                   \
    } while (0)

    // prologue: stages 0,1 filled; stage 0 guaranteed done
    FILL_TILE(0, 0);
    FILL_TILE(1, 16);
    asm volatile("cp.async.wait_group 1;" ::: "memory");
    __syncthreads();

    int st = 0, st2 = 2;     // st = t%3, st2 = (t+2)%3
    for (int t = 0; ; ) {
        const bool have2 = (t + 2 < T);
        if (have2) FILL_TILE(st2, 16 * (t + 2));

        const unsigned ao = a_rd + (unsigned)(st * ASTAGE_B);
        const unsigned bo = b_rd + (unsigned)(st * BSTAGE_B);
#pragma unroll
        for (int k = 0; k < 16; ++k) {
            unsigned long long am[2 * GM];
            float bf[4 * GN];
#pragma unroll
            for (int g = 0; g < GM; ++g)
                asm volatile("ld.shared.v2.b64 {%0,%1},[%2];"
                             : "=l"(am[2 * g]), "=l"(am[2 * g + 1])
                             : "r"(ao + (unsigned)(k * AROW * 4 + g * 256)));
#pragma unroll
            for (int g = 0; g < GN; ++g)
                asm volatile("ld.shared.v4.f32 {%0,%1,%2,%3},[%4];"
                             : "=f"(bf[4 * g]), "=f"(bf[4 * g + 1]),
                               "=f"(bf[4 * g + 2]), "=f"(bf[4 * g + 3])
                             : "r"(bo + (unsigned)(k * BROW * 4 + g * 256)));
            unsigned long long bb[4 * GN];
#pragma unroll
            for (int qn = 0; qn < 4 * GN; ++qn) bb[qn] = pack2(bf[qn]);
#pragma unroll
            for (int i = 0; i < 2 * GM; ++i) {
#pragma unroll
                for (int qn = 0; qn < 4 * GN; ++qn) fma2(acc[i][qn], am[i], bb[qn]);
            }
        }

        if (t + 1 >= T) break;
        if (have2) asm volatile("cp.async.wait_group 1;" ::: "memory");
        else       asm volatile("cp.async.wait_group 0;" ::: "memory");
        __syncthreads();
        ++t;
        st = (st == 2) ? 0 : st + 1;
        st2 = (st2 == 2) ? 0 : st2 + 1;
    }
#undef FILL_TILE

    if (TOUT) {
        // transposed epilogue: C[n][m], row stride Mtot, bias+relu.
#pragma unroll
        for (int gn = 0; gn < GN; ++gn) {
#pragma unroll
            for (int q = 0; q < 4; ++q) {
                const int n = n0 + 64 * gn + 4 * tx + q;
                const float bq = bias[n];
#pragma unroll
                for (int g = 0; g < GM; ++g) {
                    float2 e0 = u2f(acc[2 * g][4 * gn + q]);
                    float2 e1 = u2f(acc[2 * g + 1][4 * gn + q]);
                    float4 v = make_float4(fmaxf(e0.x + bq, 0.f), fmaxf(e0.y + bq, 0.f),
                                           fmaxf(e1.x + bq, 0.f), fmaxf(e1.y + bq, 0.f));
                    *reinterpret_cast<float4*>(
                        &C[(size_t)n * Mtot + m0 + 64 * g + 4 * ty]) = v;
                }
            }
        }
    } else {
        // RED epilogue: accumulate partials straight into pre-biased C.
#pragma unroll
        for (int i = 0; i < 2 * GM; ++i) {
            const int mrow = m0 + 64 * (i >> 1) + 4 * ty + 2 * (i & 1);
            float* r0 = C + (size_t)mrow * Nn;
            float* r1 = C + (size_t)(mrow + 1) * Nn;
#pragma unroll
            for (int gn = 0; gn < GN; ++gn) {
                const int col = n0 + 64 * gn + 4 * tx;
#pragma unroll
                for (int q = 0; q < 4; ++q) {
                    float2 f = u2f(acc[i][4 * gn + q]);
                    redadd(r0 + col + q, f.x);
                    redadd(r1 + col + q, f.y);
                }
            }
        }
    }
}

// ---------------------------------------------------------------------------
extern "C" void kernel_launch(void* const* d_in, const int* in_sizes, int n_in,
                              void* d_out, int out_size) {
    const float* x  = (const float*)d_in[0];
    const float* W1 = (const float*)d_in[1];
    const float* b1 = (const float*)d_in[2];
    const float* W2 = (const float*)d_in[3];
    const float* b2 = (const float*)d_in[4];
    float* out = (float*)d_out;

    float* featT = nullptr;
    float* hT = nullptr;
    cudaGetSymbolAddress((void**)&featT, g_featT);
    cudaGetSymbolAddress((void**)&hT, g_hT);

    // 0) zero featT + pre-fill out with bias rows (RED targets)
    init_kernel<<<672, 256>>>(b2, out);

    // 1) reduction: 4096 CTAs (1/8 slab each) -> featT [128][768]
    reduce_kernel<<<4096, 256>>>(x);

    // 2) hT = relu(feat @ W1 + b1)^T: tile 64x64, grid 24x12 = 288 CTAs
    gemm_kernel<1, 1, true><<<dim3(24, 12, 1), 256>>>(featT, W1, b1, hT,
                                                      768, 1536, 128);

    // 3) out += h @ W2 (split-K=8, RED epilogue): tile 128x128, 6x6x8 CTAs
    gemm_kernel<2, 2, false><<<dim3(6, 6, 8), 256>>>(hT, W2, nullptr, out,
                                                     768, 768, 192);
}

// round 12
// speedup vs baseline: 1.0487x; 1.0487x over previous
#include <cuda_runtime.h>
#include <cstdint>
#include <cstddef>

// Problem constants: B=4, C=128, N=64, HID=1536, PROJ=768
// featT: [128, 768] (k-major for GEMM1), hT: [1536, 768] (k-major for GEMM2)

__device__ float g_featT[128 * 768];
__device__ float g_hT[1536 * 768];
__device__ float g_part[8 * 768 * 768];

__device__ __forceinline__ void redadd(float* p, float v) {
    asm volatile("red.global.add.f32 [%0], %1;" :: "l"(p), "f"(v) : "memory");
}

// ---------------------------------------------------------------------------
__global__ void __launch_bounds__(256) init_feat() {
    const int i = blockIdx.x * 256 + threadIdx.x;   // 24576 float4
    reinterpret_cast<float4*>(g_featT)[i] = make_float4(0.f, 0.f, 0.f, 0.f);
}

// ---------------------------------------------------------------------------
// Kernel 1: streaming reduction, 4096 CTAs (1/8 slab = 8 d-planes, 128 KB).
// Output featT[c][m] (m = b*192 + row); h/w rows via red.global.add.
// (unchanged from R10)
// ---------------------------------------------------------------------------
__global__ void __launch_bounds__(256, 4) reduce_kernel(const float* __restrict__ x) {
    __shared__ float dpart[8 * 64];
    __shared__ float ss_s[64];
    __shared__ float sa_s[64];
    const int tid = threadIdx.x;
    if (tid < 64) { ss_s[tid] = 0.f; sa_s[tid] = 0.f; }
    __syncthreads();

    const int slab = blockIdx.x >> 3;
    const int p    = blockIdx.x & 7;
    const int warp = tid >> 5;
    const int lane = tid & 31;
    const int q    = warp & 3;
    const int half = warp >> 2;
    const int j    = lane & 15;
    const int u    = lane >> 4;

    const float4* base = reinterpret_cast<const float4*>(x) + (size_t)slab * 65536
                         + (size_t)(8 * p) * 1024 + (16 * q + u) * 16 + j;

    float hreg[8];
#pragma unroll
    for (int i = 0; i < 8; ++i) hreg[i] = 0.f;
    float w0 = 0.f, w1 = 0.f, w2 = 0.f, w3 = 0.f;

#pragma unroll
    for (int dd = 0; dd < 4; ++dd) {
        const int dl = 2 * dd + half;
        const float4* pp = base + dl * 1024;
        float dacc = 0.f;
#pragma unroll
        for (int i = 0; i < 8; ++i) {
            float4 v = __ldcs(pp + i * 32);
            float s0 = v.x * v.x, s1 = v.y * v.y, s2 = v.z * v.z, s3 = v.w * v.w;
            w0 += s0; w1 += s1; w2 += s2; w3 += s3;
            float sm = (s0 + s1) + (s2 + s3);
            hreg[i] += sm;
            dacc    += sm;
        }
        dacc += __shfl_xor_sync(0xffffffffu, dacc, 16);
        if (lane < 16) dpart[dl * 64 + q * 16 + j] = dacc;
    }

#pragma unroll
    for (int i = 0; i < 8; ++i) {
        float v = hreg[i];
        v += __shfl_xor_sync(0xffffffffu, v, 1);
        v += __shfl_xor_sync(0xffffffffu, v, 2);
        v += __shfl_xor_sync(0xffffffffu, v, 4);
        v += __shfl_xor_sync(0xffffffffu, v, 8);
        if (j == 0) atomicAdd(&ss_s[16 * q + u + 2 * i], v);
    }

    atomicAdd(&sa_s[4 * j + 0], w0);
    atomicAdd(&sa_s[4 * j + 1], w1);
    atomicAdd(&sa_s[4 * j + 2], w2);
    atomicAdd(&sa_s[4 * j + 3], w3);

    __syncthreads();

    const int b = slab >> 7;
    const int c = slab & 127;
    float* frow = g_featT + (size_t)c * 768 + b * 192;
    if (tid < 32) {
        const int dl = tid >> 2;
        const int qq = tid & 3;
        const float4* dp = reinterpret_cast<const float4*>(&dpart[dl * 64 + qq * 16]);
        float s = 0.f;
#pragma unroll
        for (int k = 0; k < 4; ++k) {
            float4 v = dp[k];
            s += (v.x + v.y) + (v.z + v.w);
        }
        s += __shfl_xor_sync(0xffffffffu, s, 1);
        s += __shfl_xor_sync(0xffffffffu, s, 2);
        if (qq == 0) frow[8 * p + dl] = s * (1.0f / 4096.0f);
    }
    if (tid < 64) {
        redadd(&frow[64 + tid], ss_s[tid] * (1.0f / 4096.0f));
    } else if (tid < 128) {
        redadd(&frow[128 + (tid - 64)], sa_s[tid - 64] * (1.0f / 4096.0f));
    }
}

// ---------------------------------------------------------------------------
// FFMA2 SGEMM (R10 + 3-stage cp.async ring, STG epilogues unchanged).
// tile (64*GM)m x (64*GN)n, BK=16, 256 threads, k-major operands, all
// staging via cp.async. wait_group 1 keeps the newest fill in flight across
// the barrier (prefetch distance 2).
// TOUT: transposed epilogue bias+relu -> C[n][m] (row stride Mtot).
// !TOUT: fp32 partials at C + z*768*768 (combined later).
// ---------------------------------------------------------------------------
__device__ __forceinline__ void fma2(unsigned long long& d,
                                     unsigned long long a,
                                     unsigned long long b) {
    asm("fma.rn.f32x2 %0, %1, %2, %0;" : "+l"(d) : "l"(a), "l"(b));
}
__device__ __forceinline__ unsigned long long pack2(float v) {
    unsigned long long r;
    asm("mov.b64 %0, {%1, %1};" : "=l"(r) : "f"(v));
    return r;
}
__device__ __forceinline__ float2 u2f(unsigned long long v) {
    float2 f;
    asm("mov.b64 {%0,%1}, %2;" : "=f"(f.x), "=f"(f.y) : "l"(v));
    return f;
}
__device__ __forceinline__ void cp_async16(uint32_t dst, const void* src) {
    asm volatile("cp.async.ca.shared.global [%0], [%1], 16;"
                 :: "r"(dst), "l"(src) : "memory");
}

template <int GM, int GN, bool TOUT>
__global__ void __launch_bounds__(256, 2) gemm_kernel(const float* __restrict__ At,
                                                      const float* __restrict__ Bw,
                                                      const float* __restrict__ bias,
                                                      float* __restrict__ C,
                                                      int Mtot, int Nn, int Kc) {
    constexpr int AROW = 64 * GM;
    constexpr int BROW = 64 * GN;
    __shared__ float As[3][16][AROW];
    __shared__ float Bs[3][16][BROW];

    const int tid = threadIdx.x;
    const int tx = tid & 15;
    const int ty = tid >> 4;
    const int m0 = blockIdx.y * AROW;
    const int n0 = blockIdx.x * BROW;
    const int kstart = blockIdx.z * Kc;
    const int T = Kc >> 4;            // >= 2 for both calls

    unsigned long long acc[2 * GM][4 * GN];
#pragma unroll
    for (int i = 0; i < 2 * GM; ++i)
#pragma unroll
        for (int qn = 0; qn < 4 * GN; ++qn) acc[i][qn] = 0ull;

    const unsigned as_base = (unsigned)__cvta_generic_to_shared(&As[0][0][0]);
    const unsigned bs_base = (unsigned)__cvta_generic_to_shared(&Bs[0][0][0]);
    const unsigned a_rd = as_base + (unsigned)(ty * 16);
    const unsigned b_rd = bs_base + (unsigned)(tx * 16);
    constexpr unsigned ASTAGE_B = 16 * AROW * 4;
    constexpr unsigned BSTAGE_B = 16 * BROW * 4;

    const float* Abase = At + (size_t)kstart * Mtot + m0;
    const float* Bbase = Bw + (size_t)kstart * Nn + n0;

#define FILL_TILE(stage, trow)                                                 \
    do {                                                                       \
        _Pragma("unroll")                                                      \
        for (int i = 0; i < GM; ++i) {                                         \
            const int idx = tid + 256 * i;                                     \
            const int r = idx / (16 * GM);                                     \
            const int f4 = idx % (16 * GM);                                    \
            cp_async16(as_base + (unsigned)((stage) * ASTAGE_B +               \
                                            (r * AROW + 4 * f4) * 4),          \
                       Abase + (size_t)((trow) + r) * Mtot + 4 * f4);          \
        }                                                                      \
        _Pragma("unroll")                                                      \
        for (int i = 0; i < GN; ++i) {                                         \
            const int idx = tid + 256 * i;                                     \
            const int r = idx / (16 * GN);                                     \
            const int f4 = idx % (16 * GN);                                    \
            cp_async16(bs_base + (unsigned)((stage) * BSTAGE_B +               \
                                            (r * BROW + 4 * f4) * 4),          \
                       Bbase + (size_t)((trow) + r) * Nn + 4 * f4);            \
        }                                                                      \
        asm volatile("cp.async.commit_group;" ::: "memory");                   \
    } while (0)

    // prologue: stages 0,1 filled; stage 0 guaranteed complete
    FILL_TILE(0, 0);
    FILL_TILE(1, 16);
    asm volatile("cp.async.wait_group 1;" ::: "memory");
    __syncthreads();

    int st = 0, st2 = 2;     // st = t%3, st2 = (t+2)%3
    for (int t = 0; ; ) {
        const bool have2 = (t + 2 < T);
        if (have2) FILL_TILE(st2, 16 * (t + 2));

        const unsigned ao = a_rd + (unsigned)(st * ASTAGE_B);
        const unsigned bo = b_rd + (unsigned)(st * BSTAGE_B);
#pragma unroll
        for (int k = 0; k < 16; ++k) {
            unsigned long long am[2 * GM];
            float bf[4 * GN];
#pragma unroll
            for (int g = 0; g < GM; ++g)
                asm volatile("ld.shared.v2.b64 {%0,%1},[%2];"
                             : "=l"(am[2 * g]), "=l"(am[2 * g + 1])
                             : "r"(ao + (unsigned)(k * AROW * 4 + g * 256)));
#pragma unroll
            for (int g = 0; g < GN; ++g)
                asm volatile("ld.shared.v4.f32 {%0,%1,%2,%3},[%4];"
                             : "=f"(bf[4 * g]), "=f"(bf[4 * g + 1]),
                               "=f"(bf[4 * g + 2]), "=f"(bf[4 * g + 3])
                             : "r"(bo + (unsigned)(k * BROW * 4 + g * 256)));
            unsigned long long bb[4 * GN];
#pragma unroll
            for (int qn = 0; qn < 4 * GN; ++qn) bb[qn] = pack2(bf[qn]);
#pragma unroll
            for (int i = 0; i < 2 * GM; ++i) {
#pragma unroll
                for (int qn = 0; qn < 4 * GN; ++qn) fma2(acc[i][qn], am[i], bb[qn]);
            }
        }

        if (t + 1 >= T) break;
        if (have2) asm volatile("cp.async.wait_group 1;" ::: "memory");
        else       asm volatile("cp.async.wait_group 0;" ::: "memory");
        __syncthreads();
        ++t;
        st = (st == 2) ? 0 : st + 1;
        st2 = (st2 == 2) ? 0 : st2 + 1;
    }
#undef FILL_TILE

    if (TOUT) {
        // transposed epilogue: C[n][m], row stride Mtot, bias+relu.
#pragma unroll
        for (int gn = 0; gn < GN; ++gn) {
#pragma unroll
            for (int q = 0; q < 4; ++q) {
                const int n = n0 + 64 * gn + 4 * tx + q;
                const float bq = bias[n];
#pragma unroll
                for (int g = 0; g < GM; ++g) {
                    float2 e0 = u2f(acc[2 * g][4 * gn + q]);
                    float2 e1 = u2f(acc[2 * g + 1][4 * gn + q]);
                    float4 v = make_float4(fmaxf(e0.x + bq, 0.f), fmaxf(e0.y + bq, 0.f),
                                           fmaxf(e1.x + bq, 0.f), fmaxf(e1.y + bq, 0.f));
                    *reinterpret_cast<float4*>(
                        &C[(size_t)n * Mtot + m0 + 64 * g + 4 * ty]) = v;
                }
            }
        }
    } else {
        float* Cout = C + (size_t)blockIdx.z * 768 * 768;
#pragma unroll
        for (int i = 0; i < 2 * GM; ++i) {
            const int mrow = m0 + 64 * (i >> 1) + 4 * ty + 2 * (i & 1);
#pragma unroll
            for (int gn = 0; gn < GN; ++gn) {
                float2 f0 = u2f(acc[i][4 * gn + 0]);
                float2 f1 = u2f(acc[i][4 * gn + 1]);
                float2 f2 = u2f(acc[i][4 * gn + 2]);
                float2 f3 = u2f(acc[i][4 * gn + 3]);
                float4 lo0 = make_float4(f0.x, f1.x, f2.x, f3.x);
                float4 lo1 = make_float4(f0.y, f1.y, f2.y, f3.y);
                *reinterpret_cast<float4*>(&Cout[(size_t)mrow * Nn + n0 + 64 * gn + 4 * tx]) = lo0;
                *reinterpret_cast<float4*>(&Cout[(size_t)(mrow + 1) * Nn + n0 + 64 * gn + 4 * tx]) = lo1;
            }
        }
    }
}

// ---------------------------------------------------------------------------
// Combine split-K=8 partials + bias; 2 float4/thread, 8-deep MLP per f4.
// ---------------------------------------------------------------------------
__global__ void __launch_bounds__(256) combine_kernel(const float* __restrict__ part,
                                                      const float* __restrict__ bias,
                                                      float* __restrict__ out) {
    const float4* p = reinterpret_cast<const float4*>(part);
#pragma unroll
    for (int rep = 0; rep < 2; ++rep) {
        const int i = blockIdx.x * 512 + rep * 256 + threadIdx.x;
        float4 v[8];
#pragma unroll
        for (int z = 0; z < 8; ++z) v[z] = p[i + z * 147456];
        float4 bb = reinterpret_cast<const float4*>(bias)[i % 192];
        float4 r;
        r.x = (((v[0].x + v[1].x) + (v[2].x + v[3].x)) +
               ((v[4].x + v[5].x) + (v[6].x + v[7].x))) + bb.x;
        r.y = (((v[0].y + v[1].y) + (v[2].y + v[3].y)) +
               ((v[4].y + v[5].y) + (v[6].y + v[7].y))) + bb.y;
        r.z = (((v[0].z + v[1].z) + (v[2].z + v[3].z)) +
               ((v[4].z + v[5].z) + (v[6].z + v[7].z))) + bb.z;
        r.w = (((v[0].w + v[1].w) + (v[2].w + v[3].w)) +
               ((v[4].w + v[5].w) + (v[6].w + v[7].w))) + bb.w;
        reinterpret_cast<float4*>(out)[i] = r;
    }
}

// ---------------------------------------------------------------------------
extern "C" void kernel_launch(void* const* d_in, const int* in_sizes, int n_in,
                              void* d_out, int out_size) {
    const float* x  = (const float*)d_in[0];
    const float* W1 = (const float*)d_in[1];
    const float* b1 = (const float*)d_in[2];
    const float* W2 = (const float*)d_in[3];
    const float* b2 = (const float*)d_in[4];
    float* out = (float*)d_out;

    float* featT = nullptr;
    float* hT = nullptr;
    float* part = nullptr;
    cudaGetSymbolAddress((void**)&featT, g_featT);
    cudaGetSymbolAddress((void**)&hT, g_hT);
    cudaGetSymbolAddress((void**)&part, g_part);

    // 0) zero featT (h/w planes are RED targets)
    init_feat<<<96, 256>>>();

    // 1) reduction: 4096 CTAs (1/8 slab each) -> featT [128][768]
    reduce_kernel<<<4096, 256>>>(x);

    // 2) hT = relu(feat @ W1 + b1)^T: tile 64x64, grid 24x12 = 288 CTAs
    gemm_kernel<1, 1, true><<<dim3(24, 12, 1), 256>>>(featT, W1, b1, hT,
                                                      768, 1536, 128);

    // 3) partials = h @ W2 (split-K=8): tile 128x128, 6x6x8 = 288 CTAs
    gemm_kernel<2, 2, false><<<dim3(6, 6, 8), 256>>>(hT, W2, nullptr, part,
                                                     768, 768, 192);

    // 4) out = sum(8 partials) + b2
    combine_kernel<<<288, 256>>>(part, b2, out);
}